// round 1
// baseline (speedup 1.0000x reference)
#include <cuda_runtime.h>

// Problem constants (fixed shapes from reference)
#define BB 4
#define SS 8192
#define DD 1024
#define KK 16
#define MTOT (BB * SS)      // 32768 tokens
#define SCHUNKS 32          // S split for deterministic token->splat reduction

// ---------------- scratch (device globals; no allocations allowed) ----------
__device__ float g_values[(size_t)MTOT * DD];                  // 128 MB
__device__ float g_mixed [(size_t)MTOT * DD];                  // 128 MB
__device__ float g_aff   [(size_t)MTOT * KK];                  // 2 MB
__device__ float g_sspart[(size_t)SCHUNKS * BB * KK * DD];     // 8 MB
__device__ float g_ss    [(size_t)BB * KK * DD];               // 256 KB
__device__ float g_params[32];                                 // csq[16], m[16]

// ---------------- kernel 0: per-splat params --------------------------------
// csq[k] = ||c_k||^2 ; m[k] = -0.5 / clip(exp(ls),0.1,2)^2
__global__ __launch_bounds__(512)
void params_kernel(const float* __restrict__ centers,
                   const float* __restrict__ log_scales)
{
    const int w    = threadIdx.x >> 5;   // warp = splat index (16 warps)
    const int lane = threadIdx.x & 31;
    float s = 0.f;
    const float* c = centers + (size_t)w * DD;
    for (int d = lane; d < DD; d += 32) {
        float v = c[d];
        s = fmaf(v, v, s);
    }
    #pragma unroll
    for (int off = 16; off; off >>= 1)
        s += __shfl_xor_sync(0xffffffffu, s, off);
    if (lane == 0) {
        g_params[w] = s;
        float sc = expf(log_scales[w]);
        sc = fminf(fmaxf(sc, 0.1f), 2.0f);
        g_params[16 + w] = -0.5f / (sc * sc);
    }
}

// ---------------- kernel 1: affinities (warp per token) ---------------------
__global__ __launch_bounds__(256)
void aff_kernel(const float* __restrict__ tok,
                const float* __restrict__ centers)
{
    __shared__ float red[8][16];
    const int w     = threadIdx.x >> 5;                 // warp in block
    const int token = blockIdx.x * 8 + w;
    const int lane  = threadIdx.x & 31;

    const float* t = tok + (size_t)token * DD;

    float cross[KK];
    #pragma unroll
    for (int k = 0; k < KK; k++) cross[k] = 0.f;
    float tsq = 0.f;

    #pragma unroll
    for (int it = 0; it < DD / 128; it++) {
        const int d = it * 128 + lane * 4;
        float4 tv = *reinterpret_cast<const float4*>(t + d);
        tsq = fmaf(tv.x, tv.x, fmaf(tv.y, tv.y, fmaf(tv.z, tv.z, fmaf(tv.w, tv.w, tsq))));
        #pragma unroll
        for (int k = 0; k < KK; k++) {
            float4 cv = *reinterpret_cast<const float4*>(centers + k * DD + d);
            cross[k] = fmaf(tv.x, cv.x, fmaf(tv.y, cv.y,
                        fmaf(tv.z, cv.z, fmaf(tv.w, cv.w, cross[k]))));
        }
    }

    // butterfly reduce each cross[k] and tsq (all lanes end with totals)
    #pragma unroll
    for (int k = 0; k < KK; k++) {
        #pragma unroll
        for (int off = 16; off; off >>= 1)
            cross[k] += __shfl_xor_sync(0xffffffffu, cross[k], off);
    }
    #pragma unroll
    for (int off = 16; off; off >>= 1)
        tsq += __shfl_xor_sync(0xffffffffu, tsq, off);

    // lane 0 publishes cross[] (static register indexing), lanes 0..15 consume
    if (lane == 0) {
        #pragma unroll
        for (int k = 0; k < KK; k++) red[w][k] = cross[k];
    }
    __syncwarp();

    float a = 0.f;
    if (lane < KK) {
        float dist = fmaxf(tsq - 2.f * red[w][lane] + g_params[lane], 0.f);
        a = expf(g_params[16 + lane] * dist);   // TEMPERATURE == 1
    }
    float ssum = a;
    #pragma unroll
    for (int off = 16; off; off >>= 1)
        ssum += __shfl_xor_sync(0xffffffffu, ssum, off);
    if (lane < KK)
        g_aff[(size_t)token * KK + lane] = a / (ssum + 1e-8f);
}

// ---------------- SGEMM: C[M,N] = A[M,K] * B[K,N], row-major, fp32 ----------
// 128x128 block tile, 8x8 per thread, BK=8, 256 threads. Shapes are multiples.
__global__ __launch_bounds__(256, 2)
void sgemm128(const float* __restrict__ A, const float* __restrict__ B,
              float* __restrict__ C, int M, int N, int K)
{
    __shared__ float As[8][128];
    __shared__ float Bs[8][128];

    const int tid = threadIdx.x;
    const int bm  = blockIdx.y << 7;
    const int bn  = blockIdx.x << 7;
    const int tr  = tid >> 4;          // 0..15
    const int tc  = tid & 15;          // 0..15

    const int arow = tid >> 1;         // 0..127
    const int acol = (tid & 1) << 2;   // 0 or 4
    const int brow = tid >> 5;         // 0..7
    const int bcol = (tid & 31) << 2;  // 0..124

    const float* Ap = A + (size_t)(bm + arow) * K + acol;
    const float* Bp = B + (size_t)brow * N + bn + bcol;

    float acc[8][8];
    #pragma unroll
    for (int i = 0; i < 8; i++)
        #pragma unroll
        for (int j = 0; j < 8; j++) acc[i][j] = 0.f;

    for (int k0 = 0; k0 < K; k0 += 8) {
        float4 av = *reinterpret_cast<const float4*>(Ap);
        float4 bv = *reinterpret_cast<const float4*>(Bp);
        Ap += 8;
        Bp += (size_t)8 * N;

        As[acol + 0][arow] = av.x;
        As[acol + 1][arow] = av.y;
        As[acol + 2][arow] = av.z;
        As[acol + 3][arow] = av.w;
        *reinterpret_cast<float4*>(&Bs[brow][bcol]) = bv;
        __syncthreads();

        #pragma unroll
        for (int k = 0; k < 8; k++) {
            float4 a0 = *reinterpret_cast<const float4*>(&As[k][tr * 8]);
            float4 a1 = *reinterpret_cast<const float4*>(&As[k][tr * 8 + 4]);
            float4 b0 = *reinterpret_cast<const float4*>(&Bs[k][tc * 8]);
            float4 b1 = *reinterpret_cast<const float4*>(&Bs[k][tc * 8 + 4]);
            float ra[8] = {a0.x, a0.y, a0.z, a0.w, a1.x, a1.y, a1.z, a1.w};
            float rb[8] = {b0.x, b0.y, b0.z, b0.w, b1.x, b1.y, b1.z, b1.w};
            #pragma unroll
            for (int i = 0; i < 8; i++)
                #pragma unroll
                for (int j = 0; j < 8; j++)
                    acc[i][j] = fmaf(ra[i], rb[j], acc[i][j]);
        }
        __syncthreads();
    }

    #pragma unroll
    for (int i = 0; i < 8; i++) {
        float* Cp = C + (size_t)(bm + tr * 8 + i) * N + bn + tc * 8;
        *reinterpret_cast<float4*>(Cp) =
            make_float4(acc[i][0], acc[i][1], acc[i][2], acc[i][3]);
        *reinterpret_cast<float4*>(Cp + 4) =
            make_float4(acc[i][4], acc[i][5], acc[i][6], acc[i][7]);
    }
}

// ---------------- kernel 3: token->splat partial reduction ------------------
// grid (D/256, SCHUNKS, B); partials over S-chunks for determinism.
__global__ __launch_bounds__(256)
void splat_partial_kernel()
{
    const int d  = blockIdx.x * 256 + threadIdx.x;
    const int sc = blockIdx.y;
    const int b  = blockIdx.z;
    const int slen = SS / SCHUNKS;          // 256
    const int s0 = sc * slen;

    const float* vb = g_values + ((size_t)b * SS + s0) * DD + d;
    const float* ab = g_aff    + ((size_t)b * SS + s0) * KK;

    float acc[KK];
    #pragma unroll
    for (int k = 0; k < KK; k++) acc[k] = 0.f;

    #pragma unroll 4
    for (int s = 0; s < slen; s++) {
        float v = vb[(size_t)s * DD];
        #pragma unroll
        for (int k = 0; k < KK; k++)
            acc[k] = fmaf(__ldg(ab + s * KK + k), v, acc[k]);
    }
    #pragma unroll
    for (int k = 0; k < KK; k++)
        g_sspart[(((size_t)sc * BB + b) * KK + k) * DD + d] = acc[k];
}

// ---------------- kernel 4: reduce partials -> splat_states -----------------
__global__ __launch_bounds__(256)
void ssreduce_kernel()
{
    const int idx = blockIdx.x * 256 + threadIdx.x;   // 0..BB*KK*DD-1
    float s = 0.f;
    #pragma unroll
    for (int sc = 0; sc < SCHUNKS; sc++)
        s += g_sspart[(size_t)sc * (BB * KK * DD) + idx];
    g_ss[idx] = s;
}

// ---------------- kernel 5: splat->token mix ---------------------------------
__global__ __launch_bounds__(256)
void mix_kernel()
{
    const int gi   = blockIdx.x * 256 + threadIdx.x;  // over MTOT * (DD/4)
    const int tkn  = gi >> 8;                         // DD/4 = 256
    const int d4   = gi & 255;
    const int b    = tkn >> 13;                       // / SS

    const float*  a   = g_aff + (size_t)tkn * KK;
    const float4* ss4 = reinterpret_cast<const float4*>(g_ss)
                        + ((size_t)b * KK) * (DD / 4) + d4;

    float4 acc = make_float4(0.f, 0.f, 0.f, 0.f);
    #pragma unroll
    for (int k = 0; k < KK; k++) {
        float  ak = a[k];
        float4 sv = ss4[(size_t)k * (DD / 4)];
        acc.x = fmaf(ak, sv.x, acc.x);
        acc.y = fmaf(ak, sv.y, acc.y);
        acc.z = fmaf(ak, sv.z, acc.z);
        acc.w = fmaf(ak, sv.w, acc.w);
    }
    reinterpret_cast<float4*>(g_mixed)[gi] = acc;
}

// ---------------- launch ------------------------------------------------------
extern "C" void kernel_launch(void* const* d_in, const int* in_sizes, int n_in,
                              void* d_out, int out_size)
{
    const float* tok     = (const float*)d_in[0];
    const float* centers = (const float*)d_in[1];
    const float* logs    = (const float*)d_in[2];
    const float* Wv      = (const float*)d_in[3];
    const float* Wo      = (const float*)d_in[4];
    float* out = (float*)d_out;

    float *values, *mixed;
    cudaGetSymbolAddress((void**)&values, g_values);
    cudaGetSymbolAddress((void**)&mixed,  g_mixed);

    params_kernel<<<1, 512>>>(centers, logs);
    aff_kernel<<<MTOT / 8, 256>>>(tok, centers);
    sgemm128<<<dim3(DD / 128, MTOT / 128), 256>>>(tok, Wv, values, MTOT, DD, DD);
    splat_partial_kernel<<<dim3(DD / 256, SCHUNKS, BB), 256>>>();
    ssreduce_kernel<<<(BB * KK * DD) / 256, 256>>>();
    mix_kernel<<<MTOT, 256>>>();
    sgemm128<<<dim3(DD / 128, MTOT / 128), 256>>>(mixed, Wo, out, MTOT, DD, DD);
}

// round 3
// speedup vs baseline: 3.1595x; 3.1595x over previous
#include <cuda_runtime.h>
#include <cstdint>

// Problem constants
#define BB 4
#define SS 8192
#define DD 1024
#define KK 16
#define MTOT (BB * SS)      // 32768 tokens
#define SCHUNKS 64          // S split for deterministic token->splat reduction

// ---------------- scratch (device globals; no allocations allowed) ----------
__device__ float g_values[(size_t)MTOT * DD];                  // 128 MB
__device__ float g_mixed [(size_t)MTOT * DD];                  // 128 MB
__device__ float g_aff   [(size_t)MTOT * KK];                  // 2 MB
__device__ float g_sspart[(size_t)SCHUNKS * BB * KK * DD];     // 16 MB
__device__ float g_ss    [(size_t)BB * KK * DD];               // 256 KB
__device__ float g_params[32];                                 // csq[16], m[16]
__device__ float g_WvT   [(size_t)DD * DD];                    // 4 MB (K-major)
__device__ float g_WoT   [(size_t)DD * DD];                    // 4 MB (K-major)

// ======================= helpers =============================================
__device__ __forceinline__ uint32_t smem_to_u32(const void* smem_ptr) {
    uint32_t addr;
    asm("{ .reg .u64 tmp; cvta.to.shared.u64 tmp, %1; cvt.u32.u64 %0, tmp; }"
        : "=r"(addr) : "l"(smem_ptr));
    return addr;
}
__device__ __forceinline__ uint32_t f2tf32(float x) {
    uint32_t r;
    asm("cvt.rn.tf32.f32 %0, %1;" : "=r"(r) : "f"(x));
    return r;
}
#define CP_ASYNC16(dst_u32, src_ptr) \
    asm volatile("cp.async.ca.shared.global [%0], [%1], 16;" \
        :: "r"(dst_u32), "l"(src_ptr) : "memory")
#define CP_COMMIT() asm volatile("cp.async.commit_group;" ::: "memory")
#define CP_WAIT1()  asm volatile("cp.async.wait_group 1;" ::: "memory")
#define CP_WAIT0()  asm volatile("cp.async.wait_group 0;" ::: "memory")

// mma.sync m16n8k8 tf32: D(4f) = A(4r) * B(2r) + D
__device__ __forceinline__ void mma_tf32(float* c, const uint32_t* a, const uint32_t* b) {
    asm volatile(
        "mma.sync.aligned.m16n8k8.row.col.f32.tf32.tf32.f32 "
        "{%0,%1,%2,%3}, {%4,%5,%6,%7}, {%8,%9}, {%0,%1,%2,%3};\n"
        : "+f"(c[0]), "+f"(c[1]), "+f"(c[2]), "+f"(c[3])
        : "r"(a[0]), "r"(a[1]), "r"(a[2]), "r"(a[3]), "r"(b[0]), "r"(b[1]));
}

// ======================= kernel 0: per-splat params ==========================
__global__ __launch_bounds__(512)
void params_kernel(const float* __restrict__ centers,
                   const float* __restrict__ log_scales)
{
    const int w    = threadIdx.x >> 5;
    const int lane = threadIdx.x & 31;
    float s = 0.f;
    const float* c = centers + (size_t)w * DD;
    for (int d = lane; d < DD; d += 32) {
        float v = c[d];
        s = fmaf(v, v, s);
    }
    #pragma unroll
    for (int off = 16; off; off >>= 1)
        s += __shfl_xor_sync(0xffffffffu, s, off);
    if (lane == 0) {
        g_params[w] = s;
        float sc = expf(log_scales[w]);
        sc = fminf(fmaxf(sc, 0.1f), 2.0f);
        g_params[16 + w] = -0.5f / (sc * sc);
    }
}

// ======================= kernel 1: affinities (warp per token) ===============
__global__ __launch_bounds__(256)
void aff_kernel(const float* __restrict__ tok,
                const float* __restrict__ centers)
{
    __shared__ float red[8][16];
    const int w     = threadIdx.x >> 5;
    const int token = blockIdx.x * 8 + w;
    const int lane  = threadIdx.x & 31;

    const float* t = tok + (size_t)token * DD;

    float cross[KK];
    #pragma unroll
    for (int k = 0; k < KK; k++) cross[k] = 0.f;
    float tsq = 0.f;

    #pragma unroll
    for (int it = 0; it < DD / 128; it++) {
        const int d = it * 128 + lane * 4;
        float4 tv = *reinterpret_cast<const float4*>(t + d);
        tsq = fmaf(tv.x, tv.x, fmaf(tv.y, tv.y, fmaf(tv.z, tv.z, fmaf(tv.w, tv.w, tsq))));
        #pragma unroll
        for (int k = 0; k < KK; k++) {
            float4 cv = *reinterpret_cast<const float4*>(centers + k * DD + d);
            cross[k] = fmaf(tv.x, cv.x, fmaf(tv.y, cv.y,
                        fmaf(tv.z, cv.z, fmaf(tv.w, cv.w, cross[k]))));
        }
    }

    #pragma unroll
    for (int k = 0; k < KK; k++) {
        #pragma unroll
        for (int off = 16; off; off >>= 1)
            cross[k] += __shfl_xor_sync(0xffffffffu, cross[k], off);
    }
    #pragma unroll
    for (int off = 16; off; off >>= 1)
        tsq += __shfl_xor_sync(0xffffffffu, tsq, off);

    if (lane == 0) {
        #pragma unroll
        for (int k = 0; k < KK; k++) red[w][k] = cross[k];
    }
    __syncwarp();

    float a = 0.f;
    if (lane < KK) {
        float dist = fmaxf(tsq - 2.f * red[w][lane] + g_params[lane], 0.f);
        a = expf(g_params[16 + lane] * dist);
    }
    float ssum = a;
    #pragma unroll
    for (int off = 16; off; off >>= 1)
        ssum += __shfl_xor_sync(0xffffffffu, ssum, off);
    if (lane < KK)
        g_aff[(size_t)token * KK + lane] = a / (ssum + 1e-8f);
}

// ======================= 1024x1024 transpose =================================
__global__ __launch_bounds__(256)
void transpose1024(const float* __restrict__ W, float* __restrict__ Wt)
{
    __shared__ float t[32][33];
    const int bx = blockIdx.x * 32, by = blockIdx.y * 32;
    int x = bx + threadIdx.x;
    #pragma unroll
    for (int i = 0; i < 32; i += 8)
        t[threadIdx.y + i][threadIdx.x] = W[(size_t)(by + threadIdx.y + i) * DD + x];
    __syncthreads();
    x = by + threadIdx.x;
    #pragma unroll
    for (int i = 0; i < 32; i += 8)
        Wt[(size_t)(bx + threadIdx.y + i) * DD + x] = t[threadIdx.x][threadIdx.y + i];
}

// ======================= tf32 mma.sync GEMM ==================================
// C[M,1024] = A[M,1024] * Bt[1024,1024]^T  (Bt K-major: Bt[n][k])
// CTA: 256 threads (8 warps), tile 128(M) x 256(N), BK=32.
// Warp grid 2x4, warp tile 64x64. Double-buffered cp.async SMEM.
#define BKG 32
#define LDP 36                         // padded row length (floats)
#define A_WORDS (128 * LDP)            // 4608 floats = 18432 B
#define B_WORDS (256 * LDP)            // 9216 floats = 36864 B
#define BUF_WORDS (A_WORDS + B_WORDS)  // 13824 floats = 55296 B
#define NKCHUNK (DD / BKG)             // 32

__device__ __forceinline__ void gemm_issue_loads(
    const float* __restrict__ A, const float* __restrict__ Bt,
    uint32_t sA, uint32_t sB, int bm, int bn, int k0, int tid)
{
    // A tile: 128 rows x 32 k = 1024 float4; 256 threads -> 4 each
    #pragma unroll
    for (int i = 0; i < 4; i++) {
        const int id  = tid + i * 256;
        const int row = id >> 3;
        const int c4  = id & 7;
        CP_ASYNC16(sA + (uint32_t)(row * LDP + c4 * 4) * 4,
                   A + (size_t)(bm + row) * DD + k0 + c4 * 4);
    }
    // B tile: 256 rows x 32 k = 2048 float4; 8 each
    #pragma unroll
    for (int i = 0; i < 8; i++) {
        const int id  = tid + i * 256;
        const int row = id >> 3;
        const int c4  = id & 7;
        CP_ASYNC16(sB + (uint32_t)(row * LDP + c4 * 4) * 4,
                   Bt + (size_t)(bn + row) * DD + k0 + c4 * 4);
    }
}

__global__ __launch_bounds__(256, 1)
void gemm_mma(const float* __restrict__ A, const float* __restrict__ Bt,
              float* __restrict__ C)
{
    extern __shared__ float smem[];   // 2 buffers: [buf][A | B]
    const int tid  = threadIdx.x;
    const int wid  = tid >> 5;
    const int lane = tid & 31;
    const int wm   = (wid >> 2) * 64;       // warp M offset (0 / 64)
    const int wn   = (wid & 3) * 64;        // warp N offset (0/64/128/192)
    const int grp  = lane >> 2;             // 0..7
    const int tig  = lane & 3;              // 0..3
    const int bm   = blockIdx.y * 128;
    const int bn   = blockIdx.x * 256;

    const uint32_t sbase = smem_to_u32(smem);

    float acc[4][8][4];
    #pragma unroll
    for (int mf = 0; mf < 4; mf++)
        #pragma unroll
        for (int nf = 0; nf < 8; nf++)
            #pragma unroll
            for (int q = 0; q < 4; q++) acc[mf][nf][q] = 0.f;

    // prologue: buffer 0
    gemm_issue_loads(A, Bt, sbase, sbase + A_WORDS * 4, bm, bn, 0, tid);
    CP_COMMIT();

    for (int kc = 0; kc < NKCHUNK; kc++) {
        const int cur = kc & 1;
        if (kc + 1 < NKCHUNK) {
            const int nxt = cur ^ 1;
            const uint32_t nb = sbase + (uint32_t)nxt * BUF_WORDS * 4;
            gemm_issue_loads(A, Bt, nb, nb + A_WORDS * 4, bm, bn, (kc + 1) * BKG, tid);
            CP_COMMIT();
            CP_WAIT1();
        } else {
            CP_WAIT0();
        }
        __syncthreads();

        const float* As = smem + (size_t)cur * BUF_WORDS;
        const float* Bs = As + A_WORDS;

        #pragma unroll
        for (int ks = 0; ks < 4; ks++) {
            const int kq = ks * 8 + tig;
            uint32_t afrag[4][4];
            #pragma unroll
            for (int mf = 0; mf < 4; mf++) {
                const int r = wm + mf * 16 + grp;
                afrag[mf][0] = f2tf32(As[r * LDP + kq]);
                afrag[mf][1] = f2tf32(As[(r + 8) * LDP + kq]);
                afrag[mf][2] = f2tf32(As[r * LDP + kq + 4]);
                afrag[mf][3] = f2tf32(As[(r + 8) * LDP + kq + 4]);
            }
            uint32_t bfrag[8][2];
            #pragma unroll
            for (int nf = 0; nf < 8; nf++) {
                const int cidx = wn + nf * 8 + grp;
                bfrag[nf][0] = f2tf32(Bs[cidx * LDP + kq]);
                bfrag[nf][1] = f2tf32(Bs[cidx * LDP + kq + 4]);
            }
            #pragma unroll
            for (int mf = 0; mf < 4; mf++)
                #pragma unroll
                for (int nf = 0; nf < 8; nf++)
                    mma_tf32(acc[mf][nf], afrag[mf], bfrag[nf]);
        }
        __syncthreads();
    }

    // epilogue
    #pragma unroll
    for (int mf = 0; mf < 4; mf++) {
        const int r0 = bm + wm + mf * 16 + grp;
        #pragma unroll
        for (int nf = 0; nf < 8; nf++) {
            const int col = bn + wn + nf * 8 + tig * 2;
            *reinterpret_cast<float2*>(C + (size_t)r0 * DD + col) =
                make_float2(acc[mf][nf][0], acc[mf][nf][1]);
            *reinterpret_cast<float2*>(C + (size_t)(r0 + 8) * DD + col) =
                make_float2(acc[mf][nf][2], acc[mf][nf][3]);
        }
    }
}

// ======================= token->splat partial reduction ======================
__global__ __launch_bounds__(256)
void splat_partial_kernel()
{
    const int d  = blockIdx.x * 256 + threadIdx.x;
    const int sc = blockIdx.y;
    const int b  = blockIdx.z;
    const int slen = SS / SCHUNKS;          // 128
    const int s0 = sc * slen;

    const float* vb = g_values + ((size_t)b * SS + s0) * DD + d;
    const float* ab = g_aff    + ((size_t)b * SS + s0) * KK;

    float acc[KK];
    #pragma unroll
    for (int k = 0; k < KK; k++) acc[k] = 0.f;

    #pragma unroll 8
    for (int s = 0; s < slen; s++) {
        float v = __ldg(vb + (size_t)s * DD);
        #pragma unroll
        for (int k = 0; k < KK; k++)
            acc[k] = fmaf(__ldg(ab + s * KK + k), v, acc[k]);
    }
    #pragma unroll
    for (int k = 0; k < KK; k++)
        g_sspart[(((size_t)sc * BB + b) * KK + k) * DD + d] = acc[k];
}

// ======================= reduce partials -> splat_states =====================
__global__ __launch_bounds__(256)
void ssreduce_kernel()
{
    const int idx = blockIdx.x * 256 + threadIdx.x;
    float s = 0.f;
    #pragma unroll
    for (int sc = 0; sc < SCHUNKS; sc++)
        s += g_sspart[(size_t)sc * (BB * KK * DD) + idx];
    g_ss[idx] = s;
}

// ======================= splat->token mix ====================================
__global__ __launch_bounds__(256)
void mix_kernel()
{
    const int gi   = blockIdx.x * 256 + threadIdx.x;  // over MTOT * (DD/4)
    const int tkn  = gi >> 8;
    const int d4   = gi & 255;
    const int b    = tkn >> 13;

    const float*  a   = g_aff + (size_t)tkn * KK;
    const float4* ss4 = reinterpret_cast<const float4*>(g_ss)
                        + ((size_t)b * KK) * (DD / 4) + d4;

    float4 acc = make_float4(0.f, 0.f, 0.f, 0.f);
    #pragma unroll
    for (int k = 0; k < KK; k++) {
        float  ak = a[k];
        float4 sv = ss4[(size_t)k * (DD / 4)];
        acc.x = fmaf(ak, sv.x, acc.x);
        acc.y = fmaf(ak, sv.y, acc.y);
        acc.z = fmaf(ak, sv.z, acc.z);
        acc.w = fmaf(ak, sv.w, acc.w);
    }
    reinterpret_cast<float4*>(g_mixed)[gi] = acc;
}

// ======================= launch ==============================================
extern "C" void kernel_launch(void* const* d_in, const int* in_sizes, int n_in,
                              void* d_out, int out_size)
{
    const float* tok     = (const float*)d_in[0];
    const float* centers = (const float*)d_in[1];
    const float* logs    = (const float*)d_in[2];
    const float* Wv      = (const float*)d_in[3];
    const float* Wo      = (const float*)d_in[4];
    float* out = (float*)d_out;

    float *values, *mixed, *wvt, *wot;
    cudaGetSymbolAddress((void**)&values, g_values);
    cudaGetSymbolAddress((void**)&mixed,  g_mixed);
    cudaGetSymbolAddress((void**)&wvt,    g_WvT);
    cudaGetSymbolAddress((void**)&wot,    g_WoT);

    const int gemm_smem = 2 * BUF_WORDS * 4;   // 110592 B
    cudaFuncSetAttribute(gemm_mma, cudaFuncAttributeMaxDynamicSharedMemorySize,
                         gemm_smem);

    params_kernel<<<1, 512>>>(centers, logs);
    transpose1024<<<dim3(32, 32), dim3(32, 8)>>>(Wv, wvt);
    transpose1024<<<dim3(32, 32), dim3(32, 8)>>>(Wo, wot);
    aff_kernel<<<MTOT / 8, 256>>>(tok, centers);

    gemm_mma<<<dim3(DD / 256, MTOT / 128), 256, gemm_smem>>>(tok, wvt, values);

    splat_partial_kernel<<<dim3(DD / 256, SCHUNKS, BB), 256>>>();
    ssreduce_kernel<<<(BB * KK * DD) / 256, 256>>>();
    mix_kernel<<<MTOT, 256>>>();

    gemm_mma<<<dim3(DD / 256, MTOT / 128), 256, gemm_smem>>>(mixed, wot, out);
}

// round 4
// speedup vs baseline: 13.3524x; 4.2261x over previous
#include <cuda_runtime.h>
#include <cstdint>

// Problem constants
#define BB 4
#define SS 8192
#define DD 1024
#define KK 16
#define MTOT (BB * SS)        // 32768 tokens
#define TS_CHUNKS 64
#define TS_SLEN (SS / TS_CHUNKS)   // 128
#define MKD (BB * KK * DD)    // 65536

// ---------------- scratch (device globals; no allocations) ------------------
__device__ float g_aff [(size_t)MTOT * KK];            // 2 MB
__device__ float g_tsp [(size_t)TS_CHUNKS * MKD];      // 16 MB  (ts partials)
__device__ float g_ts  [(size_t)MKD];                  // 256 KB (aff^T @ tok)
__device__ float g_ssp [(size_t)8 * MKD];              // 2 MB   (mini-gemm partials)
__device__ float g_ss  [(size_t)MKD];                  // 256 KB (ts @ W_v)
__device__ float g_ssw [(size_t)MKD];                  // 256 KB (ss @ W_o)
__device__ float g_params[32];                         // csq[16], m[16]

// ---------------- packed f32x2 helpers ---------------------------------------
#define FMA2(d, a, b) \
    asm("fma.rn.f32x2 %0, %1, %2, %0;" : "+l"(d) : "l"(a), "l"(b))
#define PACK2(dst, lo, hi) \
    asm("mov.b64 %0, {%1, %2};" : "=l"(dst) \
        : "r"(__float_as_uint(lo)), "r"(__float_as_uint(hi)))

typedef unsigned long long ull;

// ======================= kernel 0: per-splat params ==========================
__global__ __launch_bounds__(512)
void params_kernel(const float* __restrict__ centers,
                   const float* __restrict__ log_scales)
{
    const int w    = threadIdx.x >> 5;
    const int lane = threadIdx.x & 31;
    float s = 0.f;
    const float* c = centers + (size_t)w * DD;
    for (int d = lane; d < DD; d += 32) {
        float v = c[d];
        s = fmaf(v, v, s);
    }
    #pragma unroll
    for (int off = 16; off; off >>= 1)
        s += __shfl_xor_sync(0xffffffffu, s, off);
    if (lane == 0) {
        g_params[w] = s;
        float sc = expf(log_scales[w]);
        sc = fminf(fmaxf(sc, 0.1f), 2.0f);
        g_params[16 + w] = -0.5f / (sc * sc);
    }
}

// ======================= kernel 1: affinities (warp per token) ===============
__global__ __launch_bounds__(256)
void aff_kernel(const float* __restrict__ tok,
                const float* __restrict__ centers)
{
    __shared__ float red[8][16];
    const int w     = threadIdx.x >> 5;
    const int token = blockIdx.x * 8 + w;
    const int lane  = threadIdx.x & 31;

    const float* t = tok + (size_t)token * DD;

    float cross[KK];
    #pragma unroll
    for (int k = 0; k < KK; k++) cross[k] = 0.f;
    float tsq = 0.f;

    #pragma unroll
    for (int it = 0; it < DD / 128; it++) {
        const int d = it * 128 + lane * 4;
        float4 tv = *reinterpret_cast<const float4*>(t + d);
        tsq = fmaf(tv.x, tv.x, fmaf(tv.y, tv.y, fmaf(tv.z, tv.z, fmaf(tv.w, tv.w, tsq))));
        #pragma unroll
        for (int k = 0; k < KK; k++) {
            float4 cv = *reinterpret_cast<const float4*>(centers + k * DD + d);
            cross[k] = fmaf(tv.x, cv.x, fmaf(tv.y, cv.y,
                        fmaf(tv.z, cv.z, fmaf(tv.w, cv.w, cross[k]))));
        }
    }

    #pragma unroll
    for (int k = 0; k < KK; k++) {
        #pragma unroll
        for (int off = 16; off; off >>= 1)
            cross[k] += __shfl_xor_sync(0xffffffffu, cross[k], off);
    }
    #pragma unroll
    for (int off = 16; off; off >>= 1)
        tsq += __shfl_xor_sync(0xffffffffu, tsq, off);

    if (lane == 0) {
        #pragma unroll
        for (int k = 0; k < KK; k++) red[w][k] = cross[k];
    }
    __syncwarp();

    float a = 0.f;
    if (lane < KK) {
        float dist = fmaxf(tsq - 2.f * red[w][lane] + g_params[lane], 0.f);
        a = expf(g_params[16 + lane] * dist);
    }
    float ssum = a;
    #pragma unroll
    for (int off = 16; off; off >>= 1)
        ssum += __shfl_xor_sync(0xffffffffu, ssum, off);
    if (lane < KK)
        g_aff[(size_t)token * KK + lane] = a / (ssum + 1e-8f);
}

// ======================= kernel 2: ts partials = aff^T @ tok =================
// grid (TS_CHUNKS, BB), block 256. Thread owns d = tid*4 (full D per block).
__global__ __launch_bounds__(256)
void ts_partial_kernel(const float* __restrict__ tok)
{
    __shared__ float2 saff[TS_SLEN][KK];   // aff duplicated as (a,a) pairs, 16KB
    const int tid = threadIdx.x;
    const int ck  = blockIdx.x;
    const int b   = blockIdx.y;
    const int s0  = ck * TS_SLEN;

    // stage aff chunk (broadcast-friendly)
    for (int i = tid; i < TS_SLEN * KK; i += 256) {
        float a = g_aff[((size_t)b * SS + s0) * KK + i];
        saff[i >> 4][i & 15] = make_float2(a, a);
    }
    __syncthreads();

    const int d = tid * 4;
    const float* tp = tok + ((size_t)b * SS + s0) * DD + d;

    ull acc[KK][2];
    #pragma unroll
    for (int k = 0; k < KK; k++) { acc[k][0] = 0ull; acc[k][1] = 0ull; }

    for (int s = 0; s < TS_SLEN; s++) {
        float4 v = *reinterpret_cast<const float4*>(tp + (size_t)s * DD);
        ull vlo, vhi;
        PACK2(vlo, v.x, v.y);
        PACK2(vhi, v.z, v.w);
        #pragma unroll
        for (int k = 0; k < KK; k++) {
            ull a = *reinterpret_cast<const ull*>(&saff[s][k]);
            FMA2(acc[k][0], a, vlo);
            FMA2(acc[k][1], a, vhi);
        }
    }

    float* op = g_tsp + (size_t)ck * MKD + ((size_t)b * KK) * DD + d;
    #pragma unroll
    for (int k = 0; k < KK; k++)
        *reinterpret_cast<ulonglong2*>(op + (size_t)k * DD) =
            make_ulonglong2(acc[k][0], acc[k][1]);
}

// ======================= generic partial reduce ==============================
// dst[i] = sum_p src[p*len + i]
__global__ __launch_bounds__(256)
void reduce_kernel(const float* __restrict__ src, float* __restrict__ dst,
                   int np, int len)
{
    const int i = blockIdx.x * 256 + threadIdx.x;
    if (i >= len) return;
    float s = 0.f;
    for (int p = 0; p < np; p++)
        s += src[(size_t)p * len + i];
    dst[i] = s;
}

// ======================= mini GEMM: out = M64[64,1024] @ W[1024,1024] ========
// grid (16 n-tiles, 8 e-chunks); writes partials g_ssp[echunk][64][1024].
__global__ __launch_bounds__(256)
void smallgemm_kernel(const float* __restrict__ M64, const float* __restrict__ W)
{
    __shared__ float se[128][66];   // [e][m], padded; LDS.64 alignment OK (66 even)
    const int tid = threadIdx.x;
    const int n0  = blockIdx.x * 64;
    const int e0  = blockIdx.y * 128;

    // stage: transpose M64 chunk [64 m][128 e] -> se[e][m]
    {
        const int m0 = tid >> 5;
        const int e4 = (tid & 31) * 4;
        #pragma unroll
        for (int it = 0; it < 8; it++) {
            const int m = m0 + it * 8;
            float4 v = *reinterpret_cast<const float4*>(
                M64 + (size_t)m * DD + e0 + e4);
            se[e4 + 0][m] = v.x;
            se[e4 + 1][m] = v.y;
            se[e4 + 2][m] = v.z;
            se[e4 + 3][m] = v.w;
        }
    }
    __syncthreads();

    const int nq = tid & 63;        // n = n0 + nq
    const int mg = tid >> 6;        // 0..3 -> m base mg*16
    const float* wp = W + (size_t)e0 * DD + n0 + nq;

    ull acc[8];
    #pragma unroll
    for (int j = 0; j < 8; j++) acc[j] = 0ull;

    for (int e = 0; e < 128; e++) {
        const float w = wp[(size_t)e * DD];
        ull wd;
        PACK2(wd, w, w);
        #pragma unroll
        for (int j = 0; j < 8; j++) {
            ull a = *reinterpret_cast<const ull*>(&se[e][mg * 16 + 2 * j]);
            FMA2(acc[j], a, wd);
        }
    }

    float* dst = g_ssp + (size_t)blockIdx.y * MKD + n0 + nq;
    #pragma unroll
    for (int j = 0; j < 8; j++) {
        float2 p = *reinterpret_cast<float2*>(&acc[j]);
        dst[(size_t)(mg * 16 + 2 * j)     * DD] = p.x;
        dst[(size_t)(mg * 16 + 2 * j + 1) * DD] = p.y;
    }
}

// ======================= out = aff @ ssw =====================================
// grid (SS/256, BB); block 256 = 8 warps, warp owns 128-d slice; ssw in regs.
__global__ __launch_bounds__(256)
void out_mix_kernel(float* __restrict__ out)
{
    const int tid  = threadIdx.x;
    const int wid  = tid >> 5;
    const int lane = tid & 31;
    const int b    = blockIdx.y;
    const int s0   = blockIdx.x * 256;
    const int d    = wid * 128 + lane * 4;

    // preload ssw[b][k][d..d+3] into registers as f32x2 pairs
    ull w2[KK][2];
    #pragma unroll
    for (int k = 0; k < KK; k++) {
        float4 v = *reinterpret_cast<const float4*>(
            g_ssw + ((size_t)(b * KK + k)) * DD + d);
        PACK2(w2[k][0], v.x, v.y);
        PACK2(w2[k][1], v.z, v.w);
    }

    const float* ap = g_aff + ((size_t)b * SS + s0) * KK;
    float* op = out + ((size_t)b * SS + s0) * DD + d;

    for (int t = 0; t < 256; t++) {
        float4 a0 = *reinterpret_cast<const float4*>(ap + (size_t)t * KK);
        float4 a1 = *reinterpret_cast<const float4*>(ap + (size_t)t * KK + 4);
        float4 a2 = *reinterpret_cast<const float4*>(ap + (size_t)t * KK + 8);
        float4 a3 = *reinterpret_cast<const float4*>(ap + (size_t)t * KK + 12);
        float av[KK] = {a0.x, a0.y, a0.z, a0.w, a1.x, a1.y, a1.z, a1.w,
                        a2.x, a2.y, a2.z, a2.w, a3.x, a3.y, a3.z, a3.w};
        ull acc0 = 0ull, acc1 = 0ull;
        #pragma unroll
        for (int k = 0; k < KK; k++) {
            ull ad;
            PACK2(ad, av[k], av[k]);
            FMA2(acc0, ad, w2[k][0]);
            FMA2(acc1, ad, w2[k][1]);
        }
        *reinterpret_cast<ulonglong2*>(op + (size_t)t * DD) =
            make_ulonglong2(acc0, acc1);
    }
}

// ======================= launch ==============================================
extern "C" void kernel_launch(void* const* d_in, const int* in_sizes, int n_in,
                              void* d_out, int out_size)
{
    const float* tok     = (const float*)d_in[0];
    const float* centers = (const float*)d_in[1];
    const float* logs    = (const float*)d_in[2];
    const float* Wv      = (const float*)d_in[3];
    const float* Wo      = (const float*)d_in[4];
    float* out = (float*)d_out;

    float *tsp, *ts, *ssp, *ss, *ssw;
    cudaGetSymbolAddress((void**)&tsp, g_tsp);
    cudaGetSymbolAddress((void**)&ts,  g_ts);
    cudaGetSymbolAddress((void**)&ssp, g_ssp);
    cudaGetSymbolAddress((void**)&ss,  g_ss);
    cudaGetSymbolAddress((void**)&ssw, g_ssw);

    params_kernel<<<1, 512>>>(centers, logs);
    aff_kernel<<<MTOT / 8, 256>>>(tok, centers);

    // ts = aff^T @ tok   (partials over 64 s-chunks, then reduce)
    ts_partial_kernel<<<dim3(TS_CHUNKS, BB), 256>>>(tok);
    reduce_kernel<<<MKD / 256, 256>>>(tsp, ts, TS_CHUNKS, MKD);

    // ss = ts @ W_v
    smallgemm_kernel<<<dim3(16, 8), 256>>>(ts, Wv);
    reduce_kernel<<<MKD / 256, 256>>>(ssp, ss, 8, MKD);

    // ssw = ss @ W_o
    smallgemm_kernel<<<dim3(16, 8), 256>>>(ss, Wo);
    reduce_kernel<<<MKD / 256, 256>>>(ssp, ssw, 8, MKD);

    // out = aff @ ssw
    out_mix_kernel<<<dim3(SS / 256, BB), 256>>>(out);
}

// round 5
// speedup vs baseline: 16.7881x; 1.2573x over previous
#include <cuda_runtime.h>
#include <cstdint>

// Problem constants
#define BB 4
#define SS 8192
#define DD 1024
#define KK 16
#define MTOT (BB * SS)        // 32768 tokens
#define TS_CHUNKS 64
#define TS_SLEN (SS / TS_CHUNKS)   // 128
#define MKD (BB * KK * DD)    // 65536

// ---------------- scratch (device globals; no allocations) ------------------
__device__ float g_aff [(size_t)MTOT * KK];            // 2 MB
__device__ float g_tsp [(size_t)TS_CHUNKS * MKD];      // 16 MB  (ts partials)
__device__ float g_ts  [(size_t)MKD];                  // 256 KB (aff^T @ tok)
__device__ float g_ssp [(size_t)8 * MKD];              // 2 MB   (mini-gemm partials)
__device__ float g_ss  [(size_t)MKD];                  // 256 KB (ts @ W_v)
__device__ float g_ssw [(size_t)MKD];                  // 256 KB (ss @ W_o)
__device__ float g_params[32];                         // csq[16], m[16]

// ---------------- packed f32x2 helpers ---------------------------------------
#define FMA2(d, a, b) \
    asm("fma.rn.f32x2 %0, %1, %2, %0;" : "+l"(d) : "l"(a), "l"(b))
#define PACK2(dst, lo, hi) \
    asm("mov.b64 %0, {%1, %2};" : "=l"(dst) \
        : "r"(__float_as_uint(lo)), "r"(__float_as_uint(hi)))

typedef unsigned long long ull;

// ======================= kernel 0: per-splat params ==========================
__global__ __launch_bounds__(512)
void params_kernel(const float* __restrict__ centers,
                   const float* __restrict__ log_scales)
{
    const int w    = threadIdx.x >> 5;
    const int lane = threadIdx.x & 31;
    float s = 0.f;
    const float* c = centers + (size_t)w * DD;
    for (int d = lane; d < DD; d += 32) {
        float v = c[d];
        s = fmaf(v, v, s);
    }
    #pragma unroll
    for (int off = 16; off; off >>= 1)
        s += __shfl_xor_sync(0xffffffffu, s, off);
    if (lane == 0) {
        g_params[w] = s;
        float sc = expf(log_scales[w]);
        sc = fminf(fmaxf(sc, 0.1f), 2.0f);
        g_params[16 + w] = -0.5f / (sc * sc);
    }
}

// ======================= fused affinities + ts partials ======================
// grid (TS_CHUNKS, BB), block 256 (8 warps). Block owns 128 tokens.
// Phase A: aff (4 tokens per warp pass -> 4x less center L1 traffic).
// Phase B: ts partial accumulation; token chunk re-read hits L2.
__global__ __launch_bounds__(256, 2)
void fused_aff_ts_kernel(const float* __restrict__ tok,
                         const float* __restrict__ centers)
{
    __shared__ float2 saff[TS_SLEN][KK];   // normalized aff as (a,a) pairs, 16KB
    __shared__ float  scr [8][16];         // per-warp cross scratch

    const int tid  = threadIdx.x;
    const int w    = tid >> 5;
    const int lane = tid & 31;
    const int ck   = blockIdx.x;
    const int b    = blockIdx.y;
    const int s0   = ck * TS_SLEN;

    // ---------------- Phase A: affinities, 4 tokens per pass ----------------
    #pragma unroll 1
    for (int j = 0; j < 4; j++) {
        const int lt = w * 16 + j * 4;     // local token base (4 tokens)
        const float* tb = tok + ((size_t)b * SS + s0 + lt) * DD;

        float cross[4][KK];
        float tsq[4];
        #pragma unroll
        for (int i = 0; i < 4; i++) {
            tsq[i] = 0.f;
            #pragma unroll
            for (int k = 0; k < KK; k++) cross[i][k] = 0.f;
        }

        #pragma unroll 1
        for (int it = 0; it < DD / 128; it++) {
            const int d = it * 128 + lane * 4;
            float4 tv[4];
            #pragma unroll
            for (int i = 0; i < 4; i++) {
                tv[i] = *reinterpret_cast<const float4*>(tb + (size_t)i * DD + d);
                tsq[i] = fmaf(tv[i].x, tv[i].x, fmaf(tv[i].y, tv[i].y,
                          fmaf(tv[i].z, tv[i].z, fmaf(tv[i].w, tv[i].w, tsq[i]))));
            }
            #pragma unroll
            for (int k = 0; k < KK; k++) {
                const float4 cv = __ldg(reinterpret_cast<const float4*>(
                    centers + (size_t)k * DD + d));
                #pragma unroll
                for (int i = 0; i < 4; i++)
                    cross[i][k] = fmaf(tv[i].x, cv.x, fmaf(tv[i].y, cv.y,
                                   fmaf(tv[i].z, cv.z, fmaf(tv[i].w, cv.w, cross[i][k]))));
            }
        }

        // warp reductions
        #pragma unroll
        for (int i = 0; i < 4; i++) {
            #pragma unroll
            for (int k = 0; k < KK; k++) {
                #pragma unroll
                for (int off = 16; off; off >>= 1)
                    cross[i][k] += __shfl_xor_sync(0xffffffffu, cross[i][k], off);
            }
            #pragma unroll
            for (int off = 16; off; off >>= 1)
                tsq[i] += __shfl_xor_sync(0xffffffffu, tsq[i], off);
        }

        // finalize each of the 4 tokens
        #pragma unroll
        for (int i = 0; i < 4; i++) {
            if (lane == 0) {
                #pragma unroll
                for (int k = 0; k < KK; k++) scr[w][k] = cross[i][k];
            }
            __syncwarp();
            float a = 0.f;
            if (lane < KK) {
                float dist = fmaxf(tsq[i] - 2.f * scr[w][lane] + g_params[lane], 0.f);
                a = expf(g_params[16 + lane] * dist);
            }
            float ssum = a;
            #pragma unroll
            for (int off = 16; off; off >>= 1)
                ssum += __shfl_xor_sync(0xffffffffu, ssum, off);
            if (lane < KK) {
                const float an = a / (ssum + 1e-8f);
                saff[lt + i][lane] = make_float2(an, an);
                g_aff[((size_t)b * SS + s0 + lt + i) * KK + lane] = an;
            }
            __syncwarp();
        }
    }
    __syncthreads();

    // ---------------- Phase B: ts partial accumulation ----------------------
    const int d = tid * 4;
    const float* tp = tok + ((size_t)b * SS + s0) * DD + d;

    ull acc[KK][2];
    #pragma unroll
    for (int k = 0; k < KK; k++) { acc[k][0] = 0ull; acc[k][1] = 0ull; }

    #pragma unroll 2
    for (int s = 0; s < TS_SLEN; s++) {
        float4 v = *reinterpret_cast<const float4*>(tp + (size_t)s * DD);
        ull vlo, vhi;
        PACK2(vlo, v.x, v.y);
        PACK2(vhi, v.z, v.w);
        #pragma unroll
        for (int k = 0; k < KK; k++) {
            ull a = *reinterpret_cast<const ull*>(&saff[s][k]);
            FMA2(acc[k][0], a, vlo);
            FMA2(acc[k][1], a, vhi);
        }
    }

    float* op = g_tsp + (size_t)ck * MKD + ((size_t)b * KK) * DD + d;
    #pragma unroll
    for (int k = 0; k < KK; k++)
        *reinterpret_cast<ulonglong2*>(op + (size_t)k * DD) =
            make_ulonglong2(acc[k][0], acc[k][1]);
}

// ======================= vectorized partial reduce ===========================
// dst4[i] = sum_p src4[p*len4 + i], 4-way ILP over p
__global__ __launch_bounds__(256)
void reduce4_kernel(const float4* __restrict__ src, float4* __restrict__ dst,
                    int np, int len4)
{
    const int i = blockIdx.x * 256 + threadIdx.x;
    if (i >= len4) return;
    float4 a0 = make_float4(0,0,0,0), a1 = a0, a2 = a0, a3 = a0;
    int p = 0;
    for (; p + 4 <= np; p += 4) {
        float4 v0 = src[(size_t)(p + 0) * len4 + i];
        float4 v1 = src[(size_t)(p + 1) * len4 + i];
        float4 v2 = src[(size_t)(p + 2) * len4 + i];
        float4 v3 = src[(size_t)(p + 3) * len4 + i];
        a0.x += v0.x; a0.y += v0.y; a0.z += v0.z; a0.w += v0.w;
        a1.x += v1.x; a1.y += v1.y; a1.z += v1.z; a1.w += v1.w;
        a2.x += v2.x; a2.y += v2.y; a2.z += v2.z; a2.w += v2.w;
        a3.x += v3.x; a3.y += v3.y; a3.z += v3.z; a3.w += v3.w;
    }
    for (; p < np; p++) {
        float4 v = src[(size_t)p * len4 + i];
        a0.x += v.x; a0.y += v.y; a0.z += v.z; a0.w += v.w;
    }
    dst[i] = make_float4(a0.x + a1.x + a2.x + a3.x,
                         a0.y + a1.y + a2.y + a3.y,
                         a0.z + a1.z + a2.z + a3.z,
                         a0.w + a1.w + a2.w + a3.w);
}

// ======================= mini GEMM: out = M64[64,1024] @ W[1024,1024] ========
// grid (16 n-tiles, 8 e-chunks); writes partials g_ssp[echunk][64][1024].
__global__ __launch_bounds__(256)
void smallgemm_kernel(const float* __restrict__ M64, const float* __restrict__ W)
{
    __shared__ float se[128][66];   // [e][m], padded
    const int tid = threadIdx.x;
    const int n0  = blockIdx.x * 64;
    const int e0  = blockIdx.y * 128;

    {
        const int m0 = tid >> 5;
        const int e4 = (tid & 31) * 4;
        #pragma unroll
        for (int it = 0; it < 8; it++) {
            const int m = m0 + it * 8;
            float4 v = *reinterpret_cast<const float4*>(
                M64 + (size_t)m * DD + e0 + e4);
            se[e4 + 0][m] = v.x;
            se[e4 + 1][m] = v.y;
            se[e4 + 2][m] = v.z;
            se[e4 + 3][m] = v.w;
        }
    }
    __syncthreads();

    const int nq = tid & 63;
    const int mg = tid >> 6;
    const float* wp = W + (size_t)e0 * DD + n0 + nq;

    ull acc[8];
    #pragma unroll
    for (int j = 0; j < 8; j++) acc[j] = 0ull;

    #pragma unroll 4
    for (int e = 0; e < 128; e++) {
        const float w = wp[(size_t)e * DD];
        ull wd;
        PACK2(wd, w, w);
        #pragma unroll
        for (int j = 0; j < 8; j++) {
            ull a = *reinterpret_cast<const ull*>(&se[e][mg * 16 + 2 * j]);
            FMA2(acc[j], a, wd);
        }
    }

    float* dst = g_ssp + (size_t)blockIdx.y * MKD + n0 + nq;
    #pragma unroll
    for (int j = 0; j < 8; j++) {
        float2 p = *reinterpret_cast<float2*>(&acc[j]);
        dst[(size_t)(mg * 16 + 2 * j)     * DD] = p.x;
        dst[(size_t)(mg * 16 + 2 * j + 1) * DD] = p.y;
    }
}

// ======================= out = aff @ ssw =====================================
// grid (SS/256, BB); block 256 = 8 warps; aff staged in smem as dup pairs,
// ssw slice register-resident per warp.
__global__ __launch_bounds__(256)
void out_mix_kernel(float* __restrict__ out)
{
    __shared__ float2 sa[256][KK];   // 32KB
    const int tid  = threadIdx.x;
    const int wid  = tid >> 5;
    const int lane = tid & 31;
    const int b    = blockIdx.y;
    const int s0   = blockIdx.x * 256;

    // stage aff (coalesced): 4096 floats
    {
        const float* ap = g_aff + ((size_t)b * SS + s0) * KK;
        #pragma unroll
        for (int it = 0; it < 4; it++) {
            const int i = tid + it * 256;
            float4 v = *reinterpret_cast<const float4*>(ap + i * 4);
            sa[i >> 2][(i & 3) * 4 + 0] = make_float2(v.x, v.x);
            sa[i >> 2][(i & 3) * 4 + 1] = make_float2(v.y, v.y);
            sa[i >> 2][(i & 3) * 4 + 2] = make_float2(v.z, v.z);
            sa[i >> 2][(i & 3) * 4 + 3] = make_float2(v.w, v.w);
        }
    }
    __syncthreads();

    const int d = wid * 128 + lane * 4;

    // preload ssw[b][k][d..d+3] into registers as f32x2 pairs
    ull w2[KK][2];
    #pragma unroll
    for (int k = 0; k < KK; k++) {
        float4 v = *reinterpret_cast<const float4*>(
            g_ssw + ((size_t)(b * KK + k)) * DD + d);
        PACK2(w2[k][0], v.x, v.y);
        PACK2(w2[k][1], v.z, v.w);
    }

    float* op = out + ((size_t)b * SS + s0) * DD + d;

    #pragma unroll 2
    for (int t = 0; t < 256; t++) {
        ull acc0 = 0ull, acc1 = 0ull;
        #pragma unroll
        for (int k = 0; k < KK; k++) {
            ull ad = *reinterpret_cast<const ull*>(&sa[t][k]);
            FMA2(acc0, ad, w2[k][0]);
            FMA2(acc1, ad, w2[k][1]);
        }
        *reinterpret_cast<ulonglong2*>(op + (size_t)t * DD) =
            make_ulonglong2(acc0, acc1);
    }
}

// ======================= launch ==============================================
extern "C" void kernel_launch(void* const* d_in, const int* in_sizes, int n_in,
                              void* d_out, int out_size)
{
    const float* tok     = (const float*)d_in[0];
    const float* centers = (const float*)d_in[1];
    const float* logs    = (const float*)d_in[2];
    const float* Wv      = (const float*)d_in[3];
    const float* Wo      = (const float*)d_in[4];
    float* out = (float*)d_out;

    float *tsp, *ts, *ssp, *ss, *ssw;
    cudaGetSymbolAddress((void**)&tsp, g_tsp);
    cudaGetSymbolAddress((void**)&ts,  g_ts);
    cudaGetSymbolAddress((void**)&ssp, g_ssp);
    cudaGetSymbolAddress((void**)&ss,  g_ss);
    cudaGetSymbolAddress((void**)&ssw, g_ssw);

    params_kernel<<<1, 512>>>(centers, logs);

    // aff + ts partials fused (single DRAM pass over tokens)
    fused_aff_ts_kernel<<<dim3(TS_CHUNKS, BB), 256>>>(tok, centers);
    reduce4_kernel<<<(MKD / 4 + 255) / 256, 256>>>(
        (const float4*)tsp, (float4*)ts, TS_CHUNKS, MKD / 4);

    // ss = ts @ W_v
    smallgemm_kernel<<<dim3(16, 8), 256>>>(ts, Wv);
    reduce4_kernel<<<(MKD / 4 + 255) / 256, 256>>>(
        (const float4*)ssp, (float4*)ss, 8, MKD / 4);

    // ssw = ss @ W_o
    smallgemm_kernel<<<dim3(16, 8), 256>>>(ss, Wo);
    reduce4_kernel<<<(MKD / 4 + 255) / 256, 256>>>(
        (const float4*)ssp, (float4*)ssw, 8, MKD / 4);

    // out = aff @ ssw
    out_mix_kernel<<<dim3(SS / 256, BB), 256>>>(out);
}

// round 6
// speedup vs baseline: 19.4103x; 1.1562x over previous
#include <cuda_runtime.h>
#include <cstdint>

// Problem constants
#define BB 4
#define SS 8192
#define DD 1024
#define KK 16
#define MTOT (BB * SS)        // 32768 tokens
#define TS_CHUNKS 64
#define TS_SLEN (SS / TS_CHUNKS)   // 128
#define MKD (BB * KK * DD)    // 65536
#define SG_ECHUNKS 32         // smallgemm e-chunks (32 e each)

// ---------------- scratch (device globals; no allocations) ------------------
__device__ float g_aff [(size_t)MTOT * KK];            // 2 MB
__device__ float g_tsp [(size_t)TS_CHUNKS * MKD];      // 16 MB  (ts partials)
__device__ float g_ts  [(size_t)MKD];                  // 256 KB (aff^T @ tok)
__device__ float g_ssp [(size_t)SG_ECHUNKS * MKD];     // 8 MB   (mini-gemm partials)
__device__ float g_ss  [(size_t)MKD];                  // 256 KB (ts @ W_v)
__device__ float g_ssw [(size_t)MKD];                  // 256 KB (ss @ W_o)
__device__ float g_params[32];                         // csq[16], m[16]

// ---------------- packed f32x2 helpers ---------------------------------------
#define FMA2(d, a, b) \
    asm("fma.rn.f32x2 %0, %1, %2, %0;" : "+l"(d) : "l"(a), "l"(b))
#define PACK2(dst, lo, hi) \
    asm("mov.b64 %0, {%1, %2};" : "=l"(dst) \
        : "r"(__float_as_uint(lo)), "r"(__float_as_uint(hi)))

typedef unsigned long long ull;

// ======================= kernel 0: per-splat params ==========================
__global__ __launch_bounds__(512)
void params_kernel(const float* __restrict__ centers,
                   const float* __restrict__ log_scales)
{
    const int w    = threadIdx.x >> 5;
    const int lane = threadIdx.x & 31;
    float s = 0.f;
    const float* c = centers + (size_t)w * DD;
    for (int d = lane; d < DD; d += 32) {
        float v = c[d];
        s = fmaf(v, v, s);
    }
    #pragma unroll
    for (int off = 16; off; off >>= 1)
        s += __shfl_xor_sync(0xffffffffu, s, off);
    if (lane == 0) {
        g_params[w] = s;
        float sc = expf(log_scales[w]);
        sc = fminf(fmaxf(sc, 0.1f), 2.0f);
        g_params[16 + w] = -0.5f / (sc * sc);
    }
}

// ======================= fused affinities + ts partials ======================
// grid (TS_CHUNKS, BB), block 256 (8 warps). Block owns 128 tokens.
__global__ __launch_bounds__(256, 2)
void fused_aff_ts_kernel(const float* __restrict__ tok,
                         const float* __restrict__ centers)
{
    __shared__ float2 saff[TS_SLEN][KK];   // normalized aff as (a,a) pairs, 16KB
    __shared__ float  scr [8][16];

    const int tid  = threadIdx.x;
    const int w    = tid >> 5;
    const int lane = tid & 31;
    const int ck   = blockIdx.x;
    const int b    = blockIdx.y;
    const int s0   = ck * TS_SLEN;

    // ---------------- Phase A: affinities, 4 tokens per pass ----------------
    #pragma unroll 1
    for (int j = 0; j < 4; j++) {
        const int lt = w * 16 + j * 4;
        const float* tb = tok + ((size_t)b * SS + s0 + lt) * DD;

        float cross[4][KK];
        float tsq[4];
        #pragma unroll
        for (int i = 0; i < 4; i++) {
            tsq[i] = 0.f;
            #pragma unroll
            for (int k = 0; k < KK; k++) cross[i][k] = 0.f;
        }

        #pragma unroll 1
        for (int it = 0; it < DD / 128; it++) {
            const int d = it * 128 + lane * 4;
            float4 tv[4];
            #pragma unroll
            for (int i = 0; i < 4; i++) {
                tv[i] = *reinterpret_cast<const float4*>(tb + (size_t)i * DD + d);
                tsq[i] = fmaf(tv[i].x, tv[i].x, fmaf(tv[i].y, tv[i].y,
                          fmaf(tv[i].z, tv[i].z, fmaf(tv[i].w, tv[i].w, tsq[i]))));
            }
            #pragma unroll
            for (int k = 0; k < KK; k++) {
                const float4 cv = __ldg(reinterpret_cast<const float4*>(
                    centers + (size_t)k * DD + d));
                #pragma unroll
                for (int i = 0; i < 4; i++)
                    cross[i][k] = fmaf(tv[i].x, cv.x, fmaf(tv[i].y, cv.y,
                                   fmaf(tv[i].z, cv.z, fmaf(tv[i].w, cv.w, cross[i][k]))));
            }
        }

        #pragma unroll
        for (int i = 0; i < 4; i++) {
            #pragma unroll
            for (int k = 0; k < KK; k++) {
                #pragma unroll
                for (int off = 16; off; off >>= 1)
                    cross[i][k] += __shfl_xor_sync(0xffffffffu, cross[i][k], off);
            }
            #pragma unroll
            for (int off = 16; off; off >>= 1)
                tsq[i] += __shfl_xor_sync(0xffffffffu, tsq[i], off);
        }

        #pragma unroll
        for (int i = 0; i < 4; i++) {
            if (lane == 0) {
                #pragma unroll
                for (int k = 0; k < KK; k++) scr[w][k] = cross[i][k];
            }
            __syncwarp();
            float a = 0.f;
            if (lane < KK) {
                float dist = fmaxf(tsq[i] - 2.f * scr[w][lane] + g_params[lane], 0.f);
                a = expf(g_params[16 + lane] * dist);
            }
            float ssum = a;
            #pragma unroll
            for (int off = 16; off; off >>= 1)
                ssum += __shfl_xor_sync(0xffffffffu, ssum, off);
            if (lane < KK) {
                const float an = a / (ssum + 1e-8f);
                saff[lt + i][lane] = make_float2(an, an);
                g_aff[((size_t)b * SS + s0 + lt + i) * KK + lane] = an;
            }
            __syncwarp();
        }
    }
    __syncthreads();

    // ---------------- Phase B: ts partial accumulation ----------------------
    const int d = tid * 4;
    const float* tp = tok + ((size_t)b * SS + s0) * DD + d;

    ull acc[KK][2];
    #pragma unroll
    for (int k = 0; k < KK; k++) { acc[k][0] = 0ull; acc[k][1] = 0ull; }

    #pragma unroll 2
    for (int s = 0; s < TS_SLEN; s++) {
        float4 v = *reinterpret_cast<const float4*>(tp + (size_t)s * DD);
        ull vlo, vhi;
        PACK2(vlo, v.x, v.y);
        PACK2(vhi, v.z, v.w);
        #pragma unroll
        for (int k = 0; k < KK; k++) {
            ull a = *reinterpret_cast<const ull*>(&saff[s][k]);
            FMA2(acc[k][0], a, vlo);
            FMA2(acc[k][1], a, vhi);
        }
    }

    float* op = g_tsp + (size_t)ck * MKD + ((size_t)b * KK) * DD + d;
    #pragma unroll
    for (int k = 0; k < KK; k++)
        *reinterpret_cast<ulonglong2*>(op + (size_t)k * DD) =
            make_ulonglong2(acc[k][0], acc[k][1]);
}

// ======================= vectorized partial reduce ===========================
__global__ __launch_bounds__(256)
void reduce4_kernel(const float4* __restrict__ src, float4* __restrict__ dst,
                    int np, int len4)
{
    const int i = blockIdx.x * 256 + threadIdx.x;
    if (i >= len4) return;
    float4 a0 = make_float4(0,0,0,0), a1 = a0, a2 = a0, a3 = a0;
    int p = 0;
    for (; p + 4 <= np; p += 4) {
        float4 v0 = src[(size_t)(p + 0) * len4 + i];
        float4 v1 = src[(size_t)(p + 1) * len4 + i];
        float4 v2 = src[(size_t)(p + 2) * len4 + i];
        float4 v3 = src[(size_t)(p + 3) * len4 + i];
        a0.x += v0.x; a0.y += v0.y; a0.z += v0.z; a0.w += v0.w;
        a1.x += v1.x; a1.y += v1.y; a1.z += v1.z; a1.w += v1.w;
        a2.x += v2.x; a2.y += v2.y; a2.z += v2.z; a2.w += v2.w;
        a3.x += v3.x; a3.y += v3.y; a3.z += v3.z; a3.w += v3.w;
    }
    for (; p < np; p++) {
        float4 v = src[(size_t)p * len4 + i];
        a0.x += v.x; a0.y += v.y; a0.z += v.z; a0.w += v.w;
    }
    dst[i] = make_float4(a0.x + a1.x + a2.x + a3.x,
                         a0.y + a1.y + a2.y + a3.y,
                         a0.z + a1.z + a2.z + a3.z,
                         a0.w + a1.w + a2.w + a3.w);
}

// ======================= mini GEMM: ssp = M64[64,1024] @ W[1024,1024] ========
// grid (16 n-tiles, 32 e-chunks of 32); latency-optimized: 512 CTAs,
// W loads software-pipelined 4 deep. Partials in g_ssp[echunk][64][1024].
__global__ __launch_bounds__(256)
void smallgemm_kernel(const float* __restrict__ M64, const float* __restrict__ W)
{
    __shared__ float se[32][66];   // [e][m], padded
    const int tid = threadIdx.x;
    const int n0  = blockIdx.x * 64;
    const int e0  = blockIdx.y * 32;

    // stage: transpose M64 chunk [64 m][32 e] -> se[e][m]; 2 float4 per thread
    {
        const int m  = tid >> 2;
        const int ee = (tid & 3) * 8;
        const float* mp = M64 + (size_t)m * DD + e0 + ee;
        float4 v0 = *reinterpret_cast<const float4*>(mp);
        float4 v1 = *reinterpret_cast<const float4*>(mp + 4);
        se[ee + 0][m] = v0.x; se[ee + 1][m] = v0.y;
        se[ee + 2][m] = v0.z; se[ee + 3][m] = v0.w;
        se[ee + 4][m] = v1.x; se[ee + 5][m] = v1.y;
        se[ee + 6][m] = v1.z; se[ee + 7][m] = v1.w;
    }
    __syncthreads();

    const int nq = tid & 63;        // column n0 + nq
    const int mg = tid >> 6;        // m group: rows mg*16 .. mg*16+15
    const float* wp = W + (size_t)e0 * DD + n0 + nq;

    ull acc[8];
    #pragma unroll
    for (int j = 0; j < 8; j++) acc[j] = 0ull;

    // software pipeline: 4 W values in flight
    float wv[4], nv[4];
    #pragma unroll
    for (int q = 0; q < 4; q++) wv[q] = wp[(size_t)q * DD];

    #pragma unroll
    for (int e = 0; e < 32; e += 4) {
        if (e + 4 < 32) {
            #pragma unroll
            for (int q = 0; q < 4; q++) nv[q] = wp[(size_t)(e + 4 + q) * DD];
        }
        #pragma unroll
        for (int q = 0; q < 4; q++) {
            ull wd;
            PACK2(wd, wv[q], wv[q]);
            #pragma unroll
            for (int j = 0; j < 8; j++) {
                ull a = *reinterpret_cast<const ull*>(&se[e + q][mg * 16 + 2 * j]);
                FMA2(acc[j], a, wd);
            }
        }
        #pragma unroll
        for (int q = 0; q < 4; q++) wv[q] = nv[q];
    }

    float* dst = g_ssp + (size_t)blockIdx.y * MKD + n0 + nq;
    #pragma unroll
    for (int j = 0; j < 8; j++) {
        float2 p = *reinterpret_cast<float2*>(&acc[j]);
        dst[(size_t)(mg * 16 + 2 * j)     * DD] = p.x;
        dst[(size_t)(mg * 16 + 2 * j + 1) * DD] = p.y;
    }
}

// ======================= out = aff @ ssw =====================================
__global__ __launch_bounds__(256)
void out_mix_kernel(float* __restrict__ out)
{
    __shared__ float2 sa[256][KK];   // 32KB
    const int tid  = threadIdx.x;
    const int wid  = tid >> 5;
    const int lane = tid & 31;
    const int b    = blockIdx.y;
    const int s0   = blockIdx.x * 256;

    {
        const float* ap = g_aff + ((size_t)b * SS + s0) * KK;
        #pragma unroll
        for (int it = 0; it < 4; it++) {
            const int i = tid + it * 256;
            float4 v = *reinterpret_cast<const float4*>(ap + i * 4);
            sa[i >> 2][(i & 3) * 4 + 0] = make_float2(v.x, v.x);
            sa[i >> 2][(i & 3) * 4 + 1] = make_float2(v.y, v.y);
            sa[i >> 2][(i & 3) * 4 + 2] = make_float2(v.z, v.z);
            sa[i >> 2][(i & 3) * 4 + 3] = make_float2(v.w, v.w);
        }
    }
    __syncthreads();

    const int d = wid * 128 + lane * 4;

    ull w2[KK][2];
    #pragma unroll
    for (int k = 0; k < KK; k++) {
        float4 v = *reinterpret_cast<const float4*>(
            g_ssw + ((size_t)(b * KK + k)) * DD + d);
        PACK2(w2[k][0], v.x, v.y);
        PACK2(w2[k][1], v.z, v.w);
    }

    float* op = out + ((size_t)b * SS + s0) * DD + d;

    #pragma unroll 2
    for (int t = 0; t < 256; t++) {
        ull acc0 = 0ull, acc1 = 0ull;
        #pragma unroll
        for (int k = 0; k < KK; k++) {
            ull ad = *reinterpret_cast<const ull*>(&sa[t][k]);
            FMA2(acc0, ad, w2[k][0]);
            FMA2(acc1, ad, w2[k][1]);
        }
        *reinterpret_cast<ulonglong2*>(op + (size_t)t * DD) =
            make_ulonglong2(acc0, acc1);
    }
}

// ======================= launch ==============================================
extern "C" void kernel_launch(void* const* d_in, const int* in_sizes, int n_in,
                              void* d_out, int out_size)
{
    const float* tok     = (const float*)d_in[0];
    const float* centers = (const float*)d_in[1];
    const float* logs    = (const float*)d_in[2];
    const float* Wv      = (const float*)d_in[3];
    const float* Wo      = (const float*)d_in[4];
    float* out = (float*)d_out;

    float *tsp, *ts, *ssp, *ss, *ssw;
    cudaGetSymbolAddress((void**)&tsp, g_tsp);
    cudaGetSymbolAddress((void**)&ts,  g_ts);
    cudaGetSymbolAddress((void**)&ssp, g_ssp);
    cudaGetSymbolAddress((void**)&ss,  g_ss);
    cudaGetSymbolAddress((void**)&ssw, g_ssw);

    params_kernel<<<1, 512>>>(centers, logs);

    // aff + ts partials fused (single DRAM pass over tokens)
    fused_aff_ts_kernel<<<dim3(TS_CHUNKS, BB), 256>>>(tok, centers);
    reduce4_kernel<<<(MKD / 4 + 255) / 256, 256>>>(
        (const float4*)tsp, (float4*)ts, TS_CHUNKS, MKD / 4);

    // ss = ts @ W_v
    smallgemm_kernel<<<dim3(16, SG_ECHUNKS), 256>>>(ts, Wv);
    reduce4_kernel<<<(MKD / 4 + 255) / 256, 256>>>(
        (const float4*)ssp, (float4*)ss, SG_ECHUNKS, MKD / 4);

    // ssw = ss @ W_o
    smallgemm_kernel<<<dim3(16, SG_ECHUNKS), 256>>>(ss, Wo);
    reduce4_kernel<<<(MKD / 4 + 255) / 256, 256>>>(
        (const float4*)ssp, (float4*)ssw, SG_ECHUNKS, MKD / 4);

    // out = aff @ ssw
    out_mix_kernel<<<dim3(SS / 256, BB), 256>>>(out);
}